// round 2
// baseline (speedup 1.0000x reference)
#include <cuda_runtime.h>
#include <math.h>

// Problem constants (fixed shapes from reference)
#define BB   2
#define TT   4
#define CC   256
#define HH   128
#define WW   128
#define HEADS 8
#define DHD   32
#define NSEQ (BB*TT*WW)        // 1024
#define LLEN HH                // 128
#define MROWS (NSEQ*LLEN)      // 131072
#define C3   (3*CC)            // 768
#define ATT_SCALE 0.17677669529663687f  // 1/sqrt(32)

// ---------------- device scratch (static globals; no allocations) -------------
__device__ float g_seq[(size_t)MROWS * CC];   // 134 MB  [N*L, C]
__device__ float g_qkv[(size_t)MROWS * C3];   // 403 MB  [N*L, 3C]
__device__ float g_ao [(size_t)MROWS * CC];   // 134 MB  [N*L, C] attention out
__device__ float g_y  [(size_t)MROWS * CC];   // 134 MB  [N*L, C] proj out

// ---------------- kernel 1: gather transpose x(B,T,C,H,W) -> seq(N,L,C) -------
// For each (bt,h): seq[(bt*W+w), h, c] = x[bt, c, h, w]  (a (c,w)->(w,c) transpose)
__global__ void gather_transpose(const float* __restrict__ x) {
    __shared__ float sm[32][33];
    const int s  = blockIdx.z;            // bt*H + h
    const int bt = s >> 7;
    const int h  = s & 127;
    const int tileW = blockIdx.x * 32;
    const int tileC = blockIdx.y * 32;
    const int tx = threadIdx.x, ty = threadIdx.y;

    const float* src = x + (size_t)bt * CC * HH * WW + (size_t)h * WW; // (c,w): src[c*H*W + w]
    #pragma unroll
    for (int i = 0; i < 4; i++) {
        int c = tileC + ty + i * 8;
        int w = tileW + tx;
        sm[ty + i * 8][tx] = src[(size_t)c * (HH * WW) + w];   // coalesced over w
    }
    __syncthreads();
    float* dst = g_seq + (size_t)bt * WW * (LLEN * CC) + (size_t)h * CC; // (w,c): dst[w*L*C + c]
    #pragma unroll
    for (int i = 0; i < 4; i++) {
        int w = tileW + ty + i * 8;
        int c = tileC + tx;
        dst[(size_t)w * (LLEN * CC) + c] = sm[tx][ty + i * 8]; // coalesced over c
    }
}

// ---------------- kernel 5: scatter transpose y(N,L,C) -> out(B,T,C,H,W) ------
__global__ void scatter_transpose(float* __restrict__ out) {
    __shared__ float sm[32][33];
    const int s  = blockIdx.z;
    const int bt = s >> 7;
    const int h  = s & 127;
    const int tileW = blockIdx.x * 32;
    const int tileC = blockIdx.y * 32;
    const int tx = threadIdx.x, ty = threadIdx.y;

    const float* src = g_y + (size_t)bt * WW * (LLEN * CC) + (size_t)h * CC; // (w,c)
    #pragma unroll
    for (int i = 0; i < 4; i++) {
        int w = tileW + ty + i * 8;
        int c = tileC + tx;
        sm[ty + i * 8][tx] = src[(size_t)w * (LLEN * CC) + c]; // coalesced over c
    }
    __syncthreads();
    float* dst = out + (size_t)bt * CC * HH * WW + (size_t)h * WW; // (c,w)
    #pragma unroll
    for (int i = 0; i < 4; i++) {
        int c = tileC + ty + i * 8;
        int w = tileW + tx;
        dst[(size_t)c * (HH * WW) + w] = sm[tx][ty + i * 8];   // coalesced over w
    }
}

// ---------------- tiled SGEMM with bias: C = A[M,K] @ B[K,Nn] + bias ----------
// BM=128, BN=64, BK=16, 256 threads, 8x4 register tile per thread.
// Requires M%128==0, Nn%64==0, K%16==0 (true for both calls).
__global__ __launch_bounds__(256) void sgemm_bias(
    const float* __restrict__ A, const float* __restrict__ Bm,
    const float* __restrict__ bias, float* __restrict__ Cm,
    int Nn, int K)
{
    __shared__ float As[16][128];
    __shared__ float Bs[16][64];

    const int tid = threadIdx.x;
    const int tx  = tid & 15;     // n direction
    const int ty  = tid >> 4;     // m direction
    const int m0  = blockIdx.y * 128;
    const int n0  = blockIdx.x * 64;

    float acc[8][4];
    #pragma unroll
    for (int i = 0; i < 8; i++)
        #pragma unroll
        for (int j = 0; j < 4; j++) acc[i][j] = 0.0f;

    for (int k0 = 0; k0 < K; k0 += 16) {
        // load A tile 128x16 -> As[k][m] (transposed in smem)
        #pragma unroll
        for (int sdx = 0; sdx < 2; sdx++) {
            int f  = tid + sdx * 256;
            int r  = f >> 2;              // 0..127
            int c4 = (f & 3) * 4;         // 0,4,8,12
            float4 v = *(const float4*)(A + (size_t)(m0 + r) * K + k0 + c4);
            As[c4 + 0][r] = v.x;
            As[c4 + 1][r] = v.y;
            As[c4 + 2][r] = v.z;
            As[c4 + 3][r] = v.w;
        }
        // load B tile 16x64 -> Bs[k][n]
        {
            int r  = tid >> 4;            // 0..15
            int c4 = (tid & 15) * 4;      // 0..60
            *(float4*)&Bs[r][c4] = *(const float4*)(Bm + (size_t)(k0 + r) * Nn + n0 + c4);
        }
        __syncthreads();

        #pragma unroll
        for (int kk = 0; kk < 16; kk++) {
            float a[8], b[4];
            *(float4*)&a[0] = *(const float4*)&As[kk][ty * 8];
            *(float4*)&a[4] = *(const float4*)&As[kk][ty * 8 + 4];
            *(float4*)&b[0] = *(const float4*)&Bs[kk][tx * 4];
            #pragma unroll
            for (int i = 0; i < 8; i++)
                #pragma unroll
                for (int j = 0; j < 4; j++)
                    acc[i][j] += a[i] * b[j];
        }
        __syncthreads();
    }

    float4 bv = *(const float4*)(bias + n0 + tx * 4);
    #pragma unroll
    for (int i = 0; i < 8; i++) {
        float4 o;
        o.x = acc[i][0] + bv.x;
        o.y = acc[i][1] + bv.y;
        o.z = acc[i][2] + bv.z;
        o.w = acc[i][3] + bv.w;
        *(float4*)(Cm + (size_t)(m0 + ty * 8 + i) * Nn + n0 + tx * 4) = o;
    }
}

// ---------------- attention: one block per (n, head), 128 threads -------------
// Two-pass softmax: pass1 rowmax, pass2 exp/sum/accumulate, normalize at end.
__global__ __launch_bounds__(128) void attn_kernel(
    const float* __restrict__ qkv, const float* __restrict__ rel_bias,
    float* __restrict__ ao)
{
    __shared__ float ks[128 * 32];
    __shared__ float vs[128 * 32];

    const int nb   = blockIdx.x;
    const int n    = nb >> 3;
    const int head = nb & 7;
    const int tid  = threadIdx.x;         // = l (query row)

    const size_t base = (size_t)n * 128 * C3;
    const int qoff = head * DHD;
    const int koff = CC + head * DHD;
    const int voff = 2 * CC + head * DHD;

    // cooperative load K, V tiles (coalesced 128B rows)
    #pragma unroll
    for (int it = 0; it < 32; it++) {
        int idx = it * 128 + tid;
        int row = idx >> 5, d = idx & 31;
        ks[idx] = qkv[base + (size_t)row * C3 + koff + d];
        vs[idx] = qkv[base + (size_t)row * C3 + voff + d];
    }
    // q row into registers
    float q[32];
    const float4* qp = (const float4*)(qkv + base + (size_t)tid * C3 + qoff);
    #pragma unroll
    for (int i = 0; i < 8; i++) {
        float4 t = qp[i];
        q[i * 4 + 0] = t.x; q[i * 4 + 1] = t.y; q[i * 4 + 2] = t.z; q[i * 4 + 3] = t.w;
    }
    __syncthreads();

    const float* brow = rel_bias + ((size_t)head * 128 + tid) * 128;

    // pass 1: row max
    float rmax = -1e30f;
    for (int m4 = 0; m4 < 128; m4 += 4) {
        float4 bb = *(const float4*)(brow + m4);
        float sv[4];
        #pragma unroll
        for (int u = 0; u < 4; u++) {
            int m = m4 + u;
            float dot = 0.0f;
            #pragma unroll
            for (int d = 0; d < 32; d++) dot += q[d] * ks[m * 32 + d];
            sv[u] = dot * ATT_SCALE + ((const float*)&bb)[u];
        }
        rmax = fmaxf(rmax, fmaxf(fmaxf(sv[0], sv[1]), fmaxf(sv[2], sv[3])));
    }

    // pass 2: exp / sum / weighted V accumulate
    float sum = 0.0f;
    float acc[32];
    #pragma unroll
    for (int d = 0; d < 32; d++) acc[d] = 0.0f;

    for (int m4 = 0; m4 < 128; m4 += 4) {
        float4 bb = *(const float4*)(brow + m4);
        float sv[4];
        #pragma unroll
        for (int u = 0; u < 4; u++) {
            int m = m4 + u;
            float dot = 0.0f;
            #pragma unroll
            for (int d = 0; d < 32; d++) dot += q[d] * ks[m * 32 + d];
            sv[u] = dot * ATT_SCALE + ((const float*)&bb)[u];
        }
        #pragma unroll
        for (int u = 0; u < 4; u++) {
            float p = __expf(sv[u] - rmax);
            sum += p;
            #pragma unroll
            for (int d = 0; d < 32; d++) acc[d] += p * vs[(m4 + u) * 32 + d];
        }
    }

    const float inv = 1.0f / sum;
    float* op = ao + ((size_t)n * 128 + tid) * CC + head * DHD;
    #pragma unroll
    for (int i = 0; i < 8; i++) {
        float4 o;
        o.x = acc[i * 4 + 0] * inv;
        o.y = acc[i * 4 + 1] * inv;
        o.z = acc[i * 4 + 2] * inv;
        o.w = acc[i * 4 + 3] * inv;
        ((float4*)op)[i] = o;
    }
}

// ---------------- launch -----------------------------------------------------
extern "C" void kernel_launch(void* const* d_in, const int* in_sizes, int n_in,
                              void* d_out, int out_size)
{
    const float* x        = (const float*)d_in[0];
    const float* rel_bias = (const float*)d_in[1];
    const float* Wqkv     = (const float*)d_in[2];
    const float* bqkv     = (const float*)d_in[3];
    const float* Wout     = (const float*)d_in[4];
    const float* bout     = (const float*)d_in[5];
    float* out = (float*)d_out;

    void *pseq, *pqkv, *pao, *py;
    cudaGetSymbolAddress(&pseq, g_seq);
    cudaGetSymbolAddress(&pqkv, g_qkv);
    cudaGetSymbolAddress(&pao,  g_ao);
    cudaGetSymbolAddress(&py,   g_y);

    dim3 tb(32, 8);
    dim3 tg(WW / 32, CC / 32, BB * TT * HH);   // (4, 8, 1024)

    gather_transpose<<<tg, tb>>>(x);

    sgemm_bias<<<dim3(C3 / 64, MROWS / 128), 256>>>(
        (const float*)pseq, Wqkv, bqkv, (float*)pqkv, C3, CC);

    attn_kernel<<<NSEQ * HEADS, 128>>>(
        (const float*)pqkv, rel_bias, (float*)pao);

    sgemm_bias<<<dim3(CC / 64, MROWS / 128), 256>>>(
        (const float*)pao, Wout, bout, (float*)py, CC, CC);

    scatter_transpose<<<tg, tb>>>(out);
}

// round 3
// speedup vs baseline: 1.0020x; 1.0020x over previous
#include <cuda_runtime.h>
#include <math.h>

// Problem constants (fixed shapes from reference)
#define BB   2
#define TT   4
#define CC   256
#define HH   128
#define WW   128
#define HEADS 8
#define DHD   32
#define NSEQ (BB*TT*WW)        // 1024
#define LLEN HH                // 128
#define MROWS (NSEQ*LLEN)      // 131072
#define C3   (3*CC)            // 768
#define ATT_SCALE 0.17677669529663687f  // 1/sqrt(32)

// ---------------- device scratch (static globals; no allocations) -------------
__device__ float g_seq[(size_t)MROWS * CC];   // 134 MB  [N*L, C]
__device__ float g_qkv[(size_t)MROWS * C3];   // 403 MB  [N*L, 3C]
__device__ float g_ao [(size_t)MROWS * CC];   // 134 MB  [N*L, C] attention out
__device__ float g_y  [(size_t)MROWS * CC];   // 134 MB  [N*L, C] proj out

// ---------------- kernel 1: gather transpose x(B,T,C,H,W) -> seq(N,L,C) -------
// For each (bt,h): seq[(bt*W+w), h, c] = x[bt, c, h, w]  (a (c,w)->(w,c) transpose)
__global__ void gather_transpose(const float* __restrict__ x) {
    __shared__ float sm[32][33];
    const int s  = blockIdx.z;            // bt*H + h
    const int bt = s >> 7;
    const int h  = s & 127;
    const int tileW = blockIdx.x * 32;
    const int tileC = blockIdx.y * 32;
    const int tx = threadIdx.x, ty = threadIdx.y;

    const float* src = x + (size_t)bt * CC * HH * WW + (size_t)h * WW; // (c,w): src[c*H*W + w]
    #pragma unroll
    for (int i = 0; i < 4; i++) {
        int c = tileC + ty + i * 8;
        int w = tileW + tx;
        sm[ty + i * 8][tx] = src[(size_t)c * (HH * WW) + w];   // coalesced over w
    }
    __syncthreads();
    float* dst = g_seq + (size_t)bt * WW * (LLEN * CC) + (size_t)h * CC; // (w,c): dst[w*L*C + c]
    #pragma unroll
    for (int i = 0; i < 4; i++) {
        int w = tileW + ty + i * 8;
        int c = tileC + tx;
        dst[(size_t)w * (LLEN * CC) + c] = sm[tx][ty + i * 8]; // coalesced over c
    }
}

// ---------------- kernel 5: scatter transpose y(N,L,C) -> out(B,T,C,H,W) ------
__global__ void scatter_transpose(float* __restrict__ out) {
    __shared__ float sm[32][33];
    const int s  = blockIdx.z;
    const int bt = s >> 7;
    const int h  = s & 127;
    const int tileW = blockIdx.x * 32;
    const int tileC = blockIdx.y * 32;
    const int tx = threadIdx.x, ty = threadIdx.y;

    const float* src = g_y + (size_t)bt * WW * (LLEN * CC) + (size_t)h * CC; // (w,c)
    #pragma unroll
    for (int i = 0; i < 4; i++) {
        int w = tileW + ty + i * 8;
        int c = tileC + tx;
        sm[ty + i * 8][tx] = src[(size_t)w * (LLEN * CC) + c]; // coalesced over c
    }
    __syncthreads();
    float* dst = out + (size_t)bt * CC * HH * WW + (size_t)h * WW; // (c,w)
    #pragma unroll
    for (int i = 0; i < 4; i++) {
        int c = tileC + ty + i * 8;
        int w = tileW + tx;
        dst[(size_t)c * (HH * WW) + w] = sm[tx][ty + i * 8];   // coalesced over w
    }
}

// ---------------- tiled SGEMM with bias: C = A[M,K] @ B[K,Nn] + bias ----------
// BM=128, BN=64, BK=16, 256 threads, 8x4 register tile per thread.
// Requires M%128==0, Nn%64==0, K%16==0 (true for both calls).
__global__ __launch_bounds__(256) void sgemm_bias(
    const float* __restrict__ A, const float* __restrict__ Bm,
    const float* __restrict__ bias, float* __restrict__ Cm,
    int Nn, int K)
{
    __shared__ float As[16][128];
    __shared__ float Bs[16][64];

    const int tid = threadIdx.x;
    const int tx  = tid & 15;     // n direction
    const int ty  = tid >> 4;     // m direction
    const int m0  = blockIdx.y * 128;
    const int n0  = blockIdx.x * 64;

    float acc[8][4];
    #pragma unroll
    for (int i = 0; i < 8; i++)
        #pragma unroll
        for (int j = 0; j < 4; j++) acc[i][j] = 0.0f;

    for (int k0 = 0; k0 < K; k0 += 16) {
        // load A tile 128x16 -> As[k][m] (transposed in smem)
        #pragma unroll
        for (int sdx = 0; sdx < 2; sdx++) {
            int f  = tid + sdx * 256;
            int r  = f >> 2;              // 0..127
            int c4 = (f & 3) * 4;         // 0,4,8,12
            float4 v = *(const float4*)(A + (size_t)(m0 + r) * K + k0 + c4);
            As[c4 + 0][r] = v.x;
            As[c4 + 1][r] = v.y;
            As[c4 + 2][r] = v.z;
            As[c4 + 3][r] = v.w;
        }
        // load B tile 16x64 -> Bs[k][n]
        {
            int r  = tid >> 4;            // 0..15
            int c4 = (tid & 15) * 4;      // 0..60
            *(float4*)&Bs[r][c4] = *(const float4*)(Bm + (size_t)(k0 + r) * Nn + n0 + c4);
        }
        __syncthreads();

        #pragma unroll
        for (int kk = 0; kk < 16; kk++) {
            float a[8], b[4];
            *(float4*)&a[0] = *(const float4*)&As[kk][ty * 8];
            *(float4*)&a[4] = *(const float4*)&As[kk][ty * 8 + 4];
            *(float4*)&b[0] = *(const float4*)&Bs[kk][tx * 4];
            #pragma unroll
            for (int i = 0; i < 8; i++)
                #pragma unroll
                for (int j = 0; j < 4; j++)
                    acc[i][j] += a[i] * b[j];
        }
        __syncthreads();
    }

    float4 bv = *(const float4*)(bias + n0 + tx * 4);
    #pragma unroll
    for (int i = 0; i < 8; i++) {
        float4 o;
        o.x = acc[i][0] + bv.x;
        o.y = acc[i][1] + bv.y;
        o.z = acc[i][2] + bv.z;
        o.w = acc[i][3] + bv.w;
        *(float4*)(Cm + (size_t)(m0 + ty * 8 + i) * Nn + n0 + tx * 4) = o;
    }
}

// ---------------- attention: one block per (n, head), 128 threads -------------
// Two-pass softmax: pass1 rowmax, pass2 exp/sum/accumulate, normalize at end.
__global__ __launch_bounds__(128) void attn_kernel(
    const float* __restrict__ qkv, const float* __restrict__ rel_bias,
    float* __restrict__ ao)
{
    __shared__ float ks[128 * 32];
    __shared__ float vs[128 * 32];

    const int nb   = blockIdx.x;
    const int n    = nb >> 3;
    const int head = nb & 7;
    const int tid  = threadIdx.x;         // = l (query row)

    const size_t base = (size_t)n * 128 * C3;
    const int qoff = head * DHD;
    const int koff = CC + head * DHD;
    const int voff = 2 * CC + head * DHD;

    // cooperative load K, V tiles (coalesced 128B rows)
    #pragma unroll
    for (int it = 0; it < 32; it++) {
        int idx = it * 128 + tid;
        int row = idx >> 5, d = idx & 31;
        ks[idx] = qkv[base + (size_t)row * C3 + koff + d];
        vs[idx] = qkv[base + (size_t)row * C3 + voff + d];
    }
    // q row into registers
    float q[32];
    const float4* qp = (const float4*)(qkv + base + (size_t)tid * C3 + qoff);
    #pragma unroll
    for (int i = 0; i < 8; i++) {
        float4 t = qp[i];
        q[i * 4 + 0] = t.x; q[i * 4 + 1] = t.y; q[i * 4 + 2] = t.z; q[i * 4 + 3] = t.w;
    }
    __syncthreads();

    const float* brow = rel_bias + ((size_t)head * 128 + tid) * 128;

    // pass 1: row max
    float rmax = -1e30f;
    for (int m4 = 0; m4 < 128; m4 += 4) {
        float4 bb = *(const float4*)(brow + m4);
        float sv[4];
        #pragma unroll
        for (int u = 0; u < 4; u++) {
            int m = m4 + u;
            float dot = 0.0f;
            #pragma unroll
            for (int d = 0; d < 32; d++) dot += q[d] * ks[m * 32 + d];
            sv[u] = dot * ATT_SCALE + ((const float*)&bb)[u];
        }
        rmax = fmaxf(rmax, fmaxf(fmaxf(sv[0], sv[1]), fmaxf(sv[2], sv[3])));
    }

    // pass 2: exp / sum / weighted V accumulate
    float sum = 0.0f;
    float acc[32];
    #pragma unroll
    for (int d = 0; d < 32; d++) acc[d] = 0.0f;

    for (int m4 = 0; m4 < 128; m4 += 4) {
        float4 bb = *(const float4*)(brow + m4);
        float sv[4];
        #pragma unroll
        for (int u = 0; u < 4; u++) {
            int m = m4 + u;
            float dot = 0.0f;
            #pragma unroll
            for (int d = 0; d < 32; d++) dot += q[d] * ks[m * 32 + d];
            sv[u] = dot * ATT_SCALE + ((const float*)&bb)[u];
        }
        #pragma unroll
        for (int u = 0; u < 4; u++) {
            float p = __expf(sv[u] - rmax);
            sum += p;
            #pragma unroll
            for (int d = 0; d < 32; d++) acc[d] += p * vs[(m4 + u) * 32 + d];
        }
    }

    const float inv = 1.0f / sum;
    float* op = ao + ((size_t)n * 128 + tid) * CC + head * DHD;
    #pragma unroll
    for (int i = 0; i < 8; i++) {
        float4 o;
        o.x = acc[i * 4 + 0] * inv;
        o.y = acc[i * 4 + 1] * inv;
        o.z = acc[i * 4 + 2] * inv;
        o.w = acc[i * 4 + 3] * inv;
        ((float4*)op)[i] = o;
    }
}

// ---------------- launch -----------------------------------------------------
extern "C" void kernel_launch(void* const* d_in, const int* in_sizes, int n_in,
                              void* d_out, int out_size)
{
    const float* x        = (const float*)d_in[0];
    const float* rel_bias = (const float*)d_in[1];
    const float* Wqkv     = (const float*)d_in[2];
    const float* bqkv     = (const float*)d_in[3];
    const float* Wout     = (const float*)d_in[4];
    const float* bout     = (const float*)d_in[5];
    float* out = (float*)d_out;

    void *pseq, *pqkv, *pao, *py;
    cudaGetSymbolAddress(&pseq, g_seq);
    cudaGetSymbolAddress(&pqkv, g_qkv);
    cudaGetSymbolAddress(&pao,  g_ao);
    cudaGetSymbolAddress(&py,   g_y);

    dim3 tb(32, 8);
    dim3 tg(WW / 32, CC / 32, BB * TT * HH);   // (4, 8, 1024)

    gather_transpose<<<tg, tb>>>(x);

    sgemm_bias<<<dim3(C3 / 64, MROWS / 128), 256>>>(
        (const float*)pseq, Wqkv, bqkv, (float*)pqkv, C3, CC);

    attn_kernel<<<NSEQ * HEADS, 128>>>(
        (const float*)pqkv, rel_bias, (float*)pao);

    sgemm_bias<<<dim3(CC / 64, MROWS / 128), 256>>>(
        (const float*)pao, Wout, bout, (float*)py, CC, CC);

    scatter_transpose<<<tg, tb>>>(out);
}